// round 13
// baseline (speedup 1.0000x reference)
#include <cuda_runtime.h>

#define FULLM 0xffffffffu

typedef unsigned long long ull;

constexpr int NQ  = 10;
constexpr int DIN = 256;
constexpr int WPB = 8;      // warps (samples) per block

// ---- packed f32x2 helpers (dense encoder only) ------------------------------
__device__ __forceinline__ ull pk2(float lo, float hi) {
    ull r; asm("mov.b64 %0, {%1, %2};" : "=l"(r) : "f"(lo), "f"(hi)); return r;
}
__device__ __forceinline__ void upk2(float& lo, float& hi, ull v) {
    asm("mov.b64 {%0, %1}, %2;" : "=f"(lo), "=f"(hi) : "l"(v));
}
__device__ __forceinline__ ull fma2(ull a, ull b, ull c) {
    ull d; asm("fma.rn.f32x2 %0, %1, %2, %3;" : "=l"(d) : "l"(a), "l"(b), "l"(c)); return d;
}
__device__ __forceinline__ ull mul2(ull a, ull b) {
    ull d; asm("mul.rn.f32x2 %0, %1, %2;" : "=l"(d) : "l"(a), "l"(b)); return d;
}
__device__ __forceinline__ ull add2(ull a, ull b) {
    ull d; asm("add.rn.f32x2 %0, %1, %2;" : "=l"(d) : "l"(a), "l"(b)); return d;
}

// Heisenberg-picture closed form (validated R12, rel_err 4.2e-7):
//   E_t = <phi| C1' RY2' C2' Z_t C2 RY2 C1 |phi>,  |phi> product state.
// 4-real-state transfer recursion; see R12 derivation comment.
//   Z_q = cos psi, X_q = sin psi cos z1, Y_q = sin psi sin z1
//   E_{q-1} = R10 + R00*X_q
//   R10' = cc*(R11*Z_q + rho*Y_q); R11' = cc*(R10 + R00*X_q)
//   R00' = -ss*(R10*X_q + R00);    rho' = ss*(R11*Y_q - rho*Z_q)
//   init: R10=c0*Z0, R11=c0, R00=-s0*X0, rho=s0*Y0 ; final E_9 = R10+R00
//   out = 0.1 * sum_t E_t.

__global__ void __launch_bounds__(WPB * 32, 3)
vqc_kernel(const float* __restrict__ x, const float* __restrict__ W,
           const float* __restrict__ b, const float* __restrict__ theta,
           float* __restrict__ out, int batch)
{
    // Wp[p][d] = packed (W[d][2p], W[d][2p+1])
    __shared__ __align__(16) ull Wp[5][DIN];
    __shared__ float angs[WPB][12];  // per-warp angles (padded row)
    __shared__ float bsh[NQ];        // b[q] + theta[0][q][0]
    __shared__ float4 qp[NQ];        // (cos z1, sin z1, cos th2, sin th2)

    const int tid  = threadIdx.x;
    const int wid  = tid >> 5;
    const int lane = tid & 31;
    const int warp = blockIdx.x * WPB + wid;
    const int wclamp = (warp < batch) ? warp : (batch - 1);

    // hoist x loads: overlap DRAM latency with W staging
    const float4* xr = reinterpret_cast<const float4*>(x + (size_t)wclamp * DIN);
    float4 xv0 = xr[lane];
    float4 xv1 = xr[lane + 32];

    // W staging: flat copy with shift/and index math (no div/mod)
    {
        const ull* Wsrc = reinterpret_cast<const ull*>(W);
#pragma unroll
        for (int it = 0; it < (5 * DIN) / (WPB * 32); ++it) {
            int m = tid + it * (WPB * 32);
            int p = m >> 8;          // 0..4
            int d = m & 255;
            Wp[p][d] = Wsrc[d * 5 + p];
        }
    }
    if (tid < NQ) {
        bsh[tid] = b[tid] + theta[tid * 2 + 0];
        float z1  = theta[tid * 2 + 1];
        float th2 = theta[(NQ + tid) * 2 + 0];
        qp[tid] = make_float4(cosf(z1), sinf(z1), cosf(th2), sinf(th2));
    }
    __syncthreads();

    // ---------------- Dense encoder (packed: 2 qubits per accumulator) ------
    float ang[NQ];
    {
        ull xp[8];
        xp[0] = pk2(xv0.x, xv0.x); xp[1] = pk2(xv0.y, xv0.y);
        xp[2] = pk2(xv0.z, xv0.z); xp[3] = pk2(xv0.w, xv0.w);
        xp[4] = pk2(xv1.x, xv1.x); xp[5] = pk2(xv1.y, xv1.y);
        xp[6] = pk2(xv1.z, xv1.z); xp[7] = pk2(xv1.w, xv1.w);
#pragma unroll
        for (int p = 0; p < 5; ++p) {
            const ulonglong2* wr = reinterpret_cast<const ulonglong2*>(&Wp[p][0]);
            ulonglong2 wa = wr[2 * lane];
            ulonglong2 wb = wr[2 * lane + 1];
            ulonglong2 wc = wr[2 * lane + 64];
            ulonglong2 wd = wr[2 * lane + 65];
            ull acc2 = mul2(xp[0], wa.x);
            acc2 = fma2(xp[1], wa.y, acc2);
            acc2 = fma2(xp[2], wb.x, acc2);
            acc2 = fma2(xp[3], wb.y, acc2);
            acc2 = fma2(xp[4], wc.x, acc2);
            acc2 = fma2(xp[5], wc.y, acc2);
            acc2 = fma2(xp[6], wd.x, acc2);
            acc2 = fma2(xp[7], wd.y, acc2);
#pragma unroll
            for (int o = 16; o; o >>= 1)
                acc2 = add2(acc2, __shfl_xor_sync(FULLM, acc2, o));
            float a0, a1; upk2(a0, a1, acc2);
            ang[2 * p]     = a0 + bsh[2 * p];
            ang[2 * p + 1] = a1 + bsh[2 * p + 1];
        }
    }

    // stage angles for block-level chain (lane 0 of each warp)
    if (lane == 0) {
#pragma unroll
        for (int q = 0; q < NQ; ++q) angs[wid][q] = ang[q];
    }
    __syncthreads();

    // ---------------- Transfer-matrix chain: ONCE per block -----------------
    // warp 0, lane s < WPB handles sample s (data-parallel across lanes).
    if (wid == 0 && lane < WPB) {
        float a[NQ];
#pragma unroll
        for (int q = 0; q < NQ; ++q) a[q] = angs[lane][q];

        float sn, cs;
        float4 p0 = qp[0];
        __sincosf(a[0], &sn, &cs);
        float X = sn * p0.x, Y = sn * p0.y, Z = cs;
        float R10 = p0.z * Z;
        float R11 = p0.z;
        float R00 = -p0.w * X;
        float rho = p0.w * Y;
        float acc = 0.f;

#pragma unroll
        for (int q = 1; q < NQ; ++q) {
            float4 pq = qp[q];
            __sincosf(a[q], &sn, &cs);
            X = sn * pq.x; Y = sn * pq.y; Z = cs;
            acc += R10 + R00 * X;     // E_{q-1}: dangling X_{t+1}
            const float cc = pq.z, ss = pq.w;
            float n10 = R11 * (cc * Z) + rho * (cc * Y);
            float n11 = R10 * cc + R00 * (cc * X);
            float n00 = -(R10 * (ss * X) + R00 * ss);
            float nrh = R11 * (ss * Y) - rho * (ss * Z);
            R10 = n10; R11 = n11; R00 = n00; rho = nrh;
        }
        acc += R10 + R00;             // E_9

        int s = blockIdx.x * WPB + lane;
        if (s < batch) out[s] = acc * 0.1f;
    }
}

extern "C" void kernel_launch(void* const* d_in, const int* in_sizes, int n_in,
                              void* d_out, int out_size)
{
    const float* x  = nullptr;
    const float* W  = nullptr;
    const float* b  = nullptr;
    const float* th = nullptr;
    for (int i = 0; i < n_in; ++i) {
        int sz = in_sizes[i];
        if      (sz == 4096 * 256) x  = (const float*)d_in[i];
        else if (sz == 256 * 10)   W  = (const float*)d_in[i];
        else if (sz == 10)         b  = (const float*)d_in[i];
        else if (sz == 2 * 10 * 2) th = (const float*)d_in[i];
    }
    if (!x)  x  = (const float*)d_in[0];
    if (!W)  W  = (const float*)d_in[1];
    if (!b)  b  = (const float*)d_in[2];
    if (!th) th = (const float*)d_in[3];

    int batch = out_size;
    int blocks = (batch + WPB - 1) / WPB;
    vqc_kernel<<<blocks, WPB * 32>>>(x, W, b, th, (float*)d_out, batch);
}

// round 14
// speedup vs baseline: 1.2904x; 1.2904x over previous
#include <cuda_runtime.h>

#define FULLM 0xffffffffu

typedef unsigned long long ull;

constexpr int NQ  = 10;
constexpr int DIN = 256;
constexpr int WPB = 4;      // warps per block; 2 samples per warp -> 8 samples/block

// ---- packed f32x2 helpers ----------------------------------------------------
__device__ __forceinline__ ull pk2(float lo, float hi) {
    ull r; asm("mov.b64 %0, {%1, %2};" : "=l"(r) : "f"(lo), "f"(hi)); return r;
}
__device__ __forceinline__ void upk2(float& lo, float& hi, ull v) {
    asm("mov.b64 {%0, %1}, %2;" : "=f"(lo), "=f"(hi) : "l"(v));
}
__device__ __forceinline__ ull fma2(ull a, ull b, ull c) {
    ull d; asm("fma.rn.f32x2 %0, %1, %2, %3;" : "=l"(d) : "l"(a), "l"(b), "l"(c)); return d;
}
__device__ __forceinline__ ull mul2(ull a, ull b) {
    ull d; asm("mul.rn.f32x2 %0, %1, %2;" : "=l"(d) : "l"(a), "l"(b)); return d;
}
__device__ __forceinline__ ull add2(ull a, ull b) {
    ull d; asm("add.rn.f32x2 %0, %1, %2;" : "=l"(d) : "l"(a), "l"(b)); return d;
}

// Heisenberg-picture closed form (validated R12/R13, rel_err 4.2e-7):
//   Z_q = cos psi, X_q = sin psi cos z1, Y_q = sin psi sin z1
//   E_{q-1} = R10 + R00*X_q
//   R10' = cc*(R11*Z_q + rho*Y_q); R11' = cc*(R10 + R00*X_q)
//   R00' = -ss*(R10*X_q + R00);    rho' = ss*(R11*Y_q - rho*Z_q)
//   init: R10=c0*Z0, R11=c0, R00=-s0*X0, rho=s0*Y0 ; final E_9 = R10+R00
//   out = 0.1 * sum_t E_t.

__global__ void __launch_bounds__(WPB * 32, 6)
vqc_kernel(const float* __restrict__ x, const float* __restrict__ W,
           const float* __restrict__ b, const float* __restrict__ theta,
           float* __restrict__ out, int batch)
{
    // Wp[p][d] = packed (W[d][2p], W[d][2p+1])
    __shared__ __align__(16) ull Wp[5][DIN];
    __shared__ float bsh[NQ];        // b[q] + theta[0][q][0]
    __shared__ float4 qp[NQ];        // (cos z1, sin z1, cos th2, sin th2)

    const int tid  = threadIdx.x;
    const int wid  = tid >> 5;
    const int lane = tid & 31;
    const int hl   = lane & 15;      // lane within half-warp
    const int side = lane >> 4;      // 0 = sample A, 1 = sample B

    // sample index: 2 per warp (A in lanes 0-15, B in 16-31)
    int s = blockIdx.x * (2 * WPB) + (wid << 1) + side;
    const int sc = (s < batch) ? s : (batch - 1);

    // hoist x loads (overlap DRAM latency with W staging)
    // lane covers d = 4*hl + 64*m + {0..3},  m = 0..3  (16 floats per lane)
    const float4* xr = reinterpret_cast<const float4*>(x + (size_t)sc * DIN);
    float4 xv0 = xr[hl];
    float4 xv1 = xr[hl + 16];
    float4 xv2 = xr[hl + 32];
    float4 xv3 = xr[hl + 48];

    // W staging: flat copy (no div/mod)
    {
        const ull* Wsrc = reinterpret_cast<const ull*>(W);
#pragma unroll
        for (int it = 0; it < (5 * DIN) / (WPB * 32); ++it) {
            int m = tid + it * (WPB * 32);
            int p = m >> 8;
            int d = m & 255;
            Wp[p][d] = Wsrc[d * 5 + p];
        }
    }
    if (tid < NQ) {
        bsh[tid] = b[tid] + theta[tid * 2 + 0];
        float z1  = theta[tid * 2 + 1];
        float th2 = theta[(NQ + tid) * 2 + 0];
        qp[tid] = make_float4(cosf(z1), sinf(z1), cosf(th2), sinf(th2));
    }
    __syncthreads();

    // ---------------- Dense encoder: 2 samples/warp, packed 2q/accumulator --
    float ang[NQ];
    {
        ull xp[16];
        xp[0]  = pk2(xv0.x, xv0.x); xp[1]  = pk2(xv0.y, xv0.y);
        xp[2]  = pk2(xv0.z, xv0.z); xp[3]  = pk2(xv0.w, xv0.w);
        xp[4]  = pk2(xv1.x, xv1.x); xp[5]  = pk2(xv1.y, xv1.y);
        xp[6]  = pk2(xv1.z, xv1.z); xp[7]  = pk2(xv1.w, xv1.w);
        xp[8]  = pk2(xv2.x, xv2.x); xp[9]  = pk2(xv2.y, xv2.y);
        xp[10] = pk2(xv2.z, xv2.z); xp[11] = pk2(xv2.w, xv2.w);
        xp[12] = pk2(xv3.x, xv3.x); xp[13] = pk2(xv3.y, xv3.y);
        xp[14] = pk2(xv3.z, xv3.z); xp[15] = pk2(xv3.w, xv3.w);
#pragma unroll
        for (int p = 0; p < 5; ++p) {
            const ulonglong2* wr = reinterpret_cast<const ulonglong2*>(&Wp[p][0]);
            ull acc2 = 0;
#pragma unroll
            for (int m = 0; m < 4; ++m) {
                // d = 4*(hl+16m) + {0..3} -> ulonglong2 elems 2*(hl+16m), +1
                ulonglong2 wa = wr[2 * (hl + 16 * m)];
                ulonglong2 wb = wr[2 * (hl + 16 * m) + 1];
                acc2 = fma2(xp[4 * m + 0], wa.x, acc2);
                acc2 = fma2(xp[4 * m + 1], wa.y, acc2);
                acc2 = fma2(xp[4 * m + 2], wb.x, acc2);
                acc2 = fma2(xp[4 * m + 3], wb.y, acc2);
            }
            // butterfly within 16-lane halves
#pragma unroll
            for (int o = 8; o; o >>= 1)
                acc2 = add2(acc2, __shfl_xor_sync(FULLM, acc2, o));
            float a0, a1; upk2(a0, a1, acc2);
            ang[2 * p]     = a0 + bsh[2 * p];
            ang[2 * p + 1] = a1 + bsh[2 * p + 1];
        }
    }

    // ---------------- Transfer-matrix chain (per lane, own half's sample) ---
    float sn, cs;
    float4 p0 = qp[0];
    __sincosf(ang[0], &sn, &cs);
    float X = sn * p0.x, Y = sn * p0.y, Z = cs;
    float R10 = p0.z * Z;
    float R11 = p0.z;
    float R00 = -p0.w * X;
    float rho = p0.w * Y;
    float acc = 0.f;

#pragma unroll
    for (int q = 1; q < NQ; ++q) {
        float4 pq = qp[q];
        __sincosf(ang[q], &sn, &cs);
        X = sn * pq.x; Y = sn * pq.y; Z = cs;
        acc += R10 + R00 * X;     // E_{q-1}: dangling X_{t+1}
        const float cc = pq.z, ss = pq.w;
        float n10 = R11 * (cc * Z) + rho * (cc * Y);
        float n11 = R10 * cc + R00 * (cc * X);
        float n00 = -(R10 * (ss * X) + R00 * ss);
        float nrh = R11 * (ss * Y) - rho * (ss * Z);
        R10 = n10; R11 = n11; R00 = n00; rho = nrh;
    }
    acc += R10 + R00;             // E_9

    if (hl == 0 && s < batch) out[s] = acc * 0.1f;
}

extern "C" void kernel_launch(void* const* d_in, const int* in_sizes, int n_in,
                              void* d_out, int out_size)
{
    const float* x  = nullptr;
    const float* W  = nullptr;
    const float* b  = nullptr;
    const float* th = nullptr;
    for (int i = 0; i < n_in; ++i) {
        int sz = in_sizes[i];
        if      (sz == 4096 * 256) x  = (const float*)d_in[i];
        else if (sz == 256 * 10)   W  = (const float*)d_in[i];
        else if (sz == 10)         b  = (const float*)d_in[i];
        else if (sz == 2 * 10 * 2) th = (const float*)d_in[i];
    }
    if (!x)  x  = (const float*)d_in[0];
    if (!W)  W  = (const float*)d_in[1];
    if (!b)  b  = (const float*)d_in[2];
    if (!th) th = (const float*)d_in[3];

    int batch = out_size;
    int spb = 2 * WPB;                       // samples per block
    int blocks = (batch + spb - 1) / spb;
    vqc_kernel<<<blocks, WPB * 32>>>(x, W, b, th, (float*)d_out, batch);
}